// round 11
// baseline (speedup 1.0000x reference)
#include <cuda_runtime.h>

#define BB    32
#define HO    30
#define NPOS  900
#define NELEM 1843200

// Scratch (no allocation allowed)
__device__ float g_raw[NPOS * 2048];    // conv output, then conv_total; [p][b][o]
__device__ float g_spk_t[NPOS * 2048];  // spk transposed to [p][b*64+c]
__device__ float g_cvt[2048 * NPOS];    // conv_total transposed to [bc][p]
__device__ float g_part[450 * 128];     // bn partials per conv block
__device__ float g_scale[64];
__device__ float g_shift[64];
__device__ float g_alpha[64 * NPOS];    // exp(-0.5/tm)
__device__ float g_rho[64 * NPOS];      // exp(-0.5/tadp)
__device__ float g_eta[64 * NPOS];      // exp(-0.5/ta)
__device__ unsigned g_ctr = 0;          // last-block ticket

__device__ __forceinline__ void cp4(unsigned dst, const float* src) {
    asm volatile("cp.async.ca.shared.global [%0], [%1], 4;" :: "r"(dst), "l"(src));
}

// ---------------------------------------------------------------------------
// Kernel 1: locally-connected conv + fused BN statistics.
// Grid (15,30), 128 threads, 2 positions/block. 4 blocks/SM (reg cap 128):
// smem 2 x 28672 B double buffer, single __syncthreads per chunk.
// ---------------------------------------------------------------------------
#define WROW 38
#define WBUF 4864            // 2*64*38 floats
#define BUFSZ 7168           // floats per buffer

__global__ __launch_bounds__(128, 4) void conv_kernel(
    const float* __restrict__ ff, const float* __restrict__ cw,
    const float* __restrict__ cbias,
    const float* __restrict__ gamma, const float* __restrict__ beta)
{
    extern __shared__ float smem[];
    const unsigned sbase = (unsigned)__cvta_generic_to_shared(smem);

    const int h   = blockIdx.y;
    const int w0  = blockIdx.x * 2;
    const int tid = threadIdx.x;
    const int lane = tid & 31;
    const int wid  = tid >> 5;

    const int base9  = (h * HO + w0) * 9;
    const int wl_pos = (lane >= 9) ? 1 : 0;
    const int wl_k   = lane - 9 * wl_pos;
    const unsigned wdst0 = (unsigned)(wl_pos * 2432 + wid * 9 + wl_k) * 4u;

    const int pe   = lane & 3;
    const int prun = wid * 8 + (lane >> 2);
    const float* ffb = ff + h * 32 + w0 + pe;

    auto stage = [&](int cb, unsigned boff) {
        if (lane < 18) {
            const float* ws = cw + (cb * 4 + wid) * 8100 + base9 + lane;
#pragma unroll
            for (int i = 0; i < 64; i++)
                cp4(sbase + boff + wdst0 + (unsigned)(i * 38) * 4u,
                    ws + i * (64 * 8100));
        }
        if (pe < 3) {
#pragma unroll
            for (int i = 0; i < 24; i++) {
                int run = i * 32 + prun;
                int kh  = run >> 8;
                int rem = run & 255;
                int pos = rem & 1;
                int bc4 = rem >> 1;
                int b   = bc4 >> 2;
                int c4  = bc4 & 3;
                cp4(sbase + boff +
                        (unsigned)(WBUF + pos * 1152 + b * 36 + c4 * 9 + kh * 3 + pe) * 4u,
                    ffb + ((b * 64 + cb * 4 + c4) << 10) + (kh << 5) + pos);
            }
        }
    };

    const int posc = wid >> 1;
    const int ltid = (wid & 1) * 32 + lane;
    const int og   = ltid & 15;
    const int bg   = ltid >> 4;

    unsigned long long acc[8][4];
#pragma unroll
    for (int ib = 0; ib < 8; ib++)
#pragma unroll
        for (int jo = 0; jo < 4; jo++) acc[ib][jo] = 0ULL;

    stage(0, 0u);
    asm volatile("cp.async.commit_group;");

#pragma unroll 1
    for (int cb = 0; cb < 16; cb++) {
        const int buf = cb & 1;
        asm volatile("cp.async.wait_group 0;");   // chunk cb resident
        __syncthreads();                          // all warps done with buf^1
        if (cb + 1 < 16) {
            stage(cb + 1, (unsigned)((buf ^ 1) * BUFSZ) * 4u);
            asm volatile("cp.async.commit_group;");
        }

        const float* Wp = smem + buf * BUFSZ + posc * 2432 + og * WROW;
        const float* Pp = smem + buf * BUFSZ + WBUF + posc * 1152 + bg * 36;
#pragma unroll
        for (int kk = 0; kk < 18; kk++) {
            unsigned long long wv[4];
#pragma unroll
            for (int jo = 0; jo < 4; jo++)
                wv[jo] = *(const unsigned long long*)(Wp + jo * (16 * WROW) + 2 * kk);
#pragma unroll
            for (int half = 0; half < 2; half++) {
                unsigned long long pv[4];
#pragma unroll
                for (int i = 0; i < 4; i++)
                    pv[i] = *(const unsigned long long*)(Pp + (half * 4 + i) * (4 * 36) + 2 * kk);
#pragma unroll
                for (int i = 0; i < 4; i++)
#pragma unroll
                    for (int jo = 0; jo < 4; jo++)
                        asm("fma.rn.f32x2 %0, %1, %2, %0;"
                            : "+l"(acc[half * 4 + i][jo]) : "l"(pv[i]), "l"(wv[jo]));
            }
        }
    }

    const int p = h * HO + w0 + posc;
    float* outp = g_raw + p * 2048;
    float cb4[4];
#pragma unroll
    for (int jo = 0; jo < 4; jo++) cb4[jo] = cbias[(og + 16 * jo) * NPOS + p];
    float ps[4] = {0.f, 0.f, 0.f, 0.f}, pq[4] = {0.f, 0.f, 0.f, 0.f};
#pragma unroll
    for (int ib = 0; ib < 8; ib++) {
        const int b = bg + 4 * ib;
#pragma unroll
        for (int jo = 0; jo < 4; jo++) {
            float2 f = *reinterpret_cast<float2*>(&acc[ib][jo]);
            float v = f.x + f.y + cb4[jo];
            outp[b * 64 + og + 16 * jo] = v;
            ps[jo] += v;
            pq[jo] += v * v;
        }
    }

    __syncthreads();
    float* red = smem;
    {
        const int slot = posc * 4 + bg;
#pragma unroll
        for (int jo = 0; jo < 4; jo++) {
            red[(og + 16 * jo) * 8 + slot]       = ps[jo];
            red[512 + (og + 16 * jo) * 8 + slot] = pq[jo];
        }
    }
    __syncthreads();
    if (tid < 64) {
        float s = 0.f, q = 0.f;
#pragma unroll
        for (int k = 0; k < 8; k++) {
            s += red[tid * 8 + k];
            q += red[512 + tid * 8 + k];
        }
        const int bid = blockIdx.y * 15 + blockIdx.x;
        g_part[bid * 128 + tid]      = s;
        g_part[bid * 128 + 64 + tid] = q;
    }
    __threadfence();
    __syncthreads();
    __shared__ unsigned s_last;
    if (tid == 0) s_last = (atomicAdd(&g_ctr, 1u) == 449u) ? 1u : 0u;
    __syncthreads();
    if (s_last) {
        const int o   = tid & 63;
        const int seg = tid >> 6;
        float s = 0.f, q = 0.f;
#pragma unroll 15
        for (int k = seg; k < 450; k += 2) {
            s += g_part[k * 128 + o];
            q += g_part[k * 128 + 64 + o];
        }
        red[seg * 64 + o]       = s;
        red[128 + seg * 64 + o] = q;
        __syncthreads();
        if (tid < 64) {
            float S = red[tid] + red[64 + tid];
            float Q = red[128 + tid] + red[192 + tid];
            const float inv = 1.f / 28800.f;
            float m   = S * inv;
            float var = Q * inv - m * m;
            float sc  = gamma[tid] * rsqrtf(var + 1e-5f);
            g_scale[tid] = sc;
            g_shift[tid] = beta[tid] - m * sc;
        }
        if (tid == 0) g_ctr = 0;
    }
}

// ---------------------------------------------------------------------------
// Kernel T1: transpose spk [bc][p] -> [p][bc]
// ---------------------------------------------------------------------------
__global__ __launch_bounds__(256) void transpose_spk(const float* __restrict__ spk)
{
    __shared__ float tile[32][33];
    const int pb = blockIdx.x * 32;
    const int cbs = blockIdx.y * 32;
    const int x = threadIdx.x & 31;
    const int y = threadIdx.x >> 5;
#pragma unroll
    for (int j = y; j < 32; j += 8) {
        int p = pb + x;
        tile[j][x] = (p < NPOS) ? spk[(cbs + j) * NPOS + p] : 0.f;
    }
    __syncthreads();
#pragma unroll
    for (int j = y; j < 32; j += 8) {
        int p = pb + j;
        if (p < NPOS) g_spk_t[p * 2048 + cbs + x] = tile[x][j];
    }
}

// ---------------------------------------------------------------------------
// Kernel P: precompute LIF decay factors per (c,p). 225 blocks x 256.
// ---------------------------------------------------------------------------
__global__ __launch_bounds__(256) void prep_kernel(
    const float* __restrict__ tm, const float* __restrict__ tadp,
    const float* __restrict__ ta)
{
    const int i = blockIdx.x * 256 + threadIdx.x;   // < 57600
    g_alpha[i] = __expf(-__fdividef(0.5f, tm[i]));
    g_rho[i]   = __expf(-__fdividef(0.5f, tadp[i]));
    g_eta[i]   = __expf(-__fdividef(0.5f, ta[i]));
}

// ---------------------------------------------------------------------------
// Kernel Z: reset conv ticket (keeps conv as 4th launch for ncu)
// ---------------------------------------------------------------------------
__global__ void zero_ctr(void) { g_ctr = 0; }

// ---------------------------------------------------------------------------
// Kernel 2: per-position recurrence GEMM + BN apply, in-place into g_raw.
// ---------------------------------------------------------------------------
__global__ __launch_bounds__(128) void rec_kernel(const float* __restrict__ lrec)
{
    const int p = blockIdx.x;
    const int t = threadIdx.x;
    __shared__ float R[64 * 68];
    __shared__ float S[32 * 68];
    __shared__ float sc[64], sh[64];

    const float4* rp = (const float4*)(lrec + p * 4096);
#pragma unroll
    for (int i = 0; i < 8; i++) {
        int idx4 = i * 128 + t;
        int c = idx4 >> 4, d0 = (idx4 & 15) << 2;
        *(float4*)&R[c * 68 + d0] = rp[idx4];
    }
    const float4* sp = (const float4*)(g_spk_t + p * 2048);
#pragma unroll
    for (int i = 0; i < 4; i++) {
        int idx4 = i * 128 + t;
        int b = idx4 >> 4, d0 = (idx4 & 15) << 2;
        *(float4*)&S[b * 68 + d0] = sp[idx4];
    }
    if (t < 64) { sc[t] = g_scale[t]; sh[t] = g_shift[t]; }
    __syncthreads();

    const int cg = t & 15;
    const int bq = t >> 4;
    float racc[4][4];
#pragma unroll
    for (int jb = 0; jb < 4; jb++)
#pragma unroll
        for (int jc = 0; jc < 4; jc++) racc[jb][jc] = 0.f;

#pragma unroll
    for (int d = 0; d < 64; d += 4) {
        float4 rv[4], sv[4];
#pragma unroll
        for (int jc = 0; jc < 4; jc++)
            rv[jc] = *(const float4*)&R[(cg + 16 * jc) * 68 + d];
#pragma unroll
        for (int jb = 0; jb < 4; jb++)
            sv[jb] = *(const float4*)&S[(4 * bq + jb) * 68 + d];
#pragma unroll
        for (int jb = 0; jb < 4; jb++)
#pragma unroll
            for (int jc = 0; jc < 4; jc++) {
                float a = racc[jb][jc];
                a = fmaf(rv[jc].x, sv[jb].x, a);
                a = fmaf(rv[jc].y, sv[jb].y, a);
                a = fmaf(rv[jc].z, sv[jb].z, a);
                a = fmaf(rv[jc].w, sv[jb].w, a);
                racc[jb][jc] = a;
            }
    }

    float* outp = g_raw + p * 2048;
#pragma unroll
    for (int jb = 0; jb < 4; jb++) {
        const int b = 4 * bq + jb;
#pragma unroll
        for (int jc = 0; jc < 4; jc++) {
            const int c = cg + 16 * jc;
            outp[b * 64 + c] = outp[b * 64 + c] * sc[c] + sh[c] + racc[jb][jc];
        }
    }
}

// ---------------------------------------------------------------------------
// Kernel T2: transpose conv_total [p][bc] -> [bc][p]
// ---------------------------------------------------------------------------
__global__ __launch_bounds__(256) void transpose_cvt(void)
{
    __shared__ float tile[32][33];
    const int pb  = blockIdx.x * 32;
    const int cbs = blockIdx.y * 32;
    const int x = threadIdx.x & 31;
    const int y = threadIdx.x >> 5;
#pragma unroll
    for (int j = y; j < 32; j += 8) {
        int p = pb + j;
        tile[j][x] = (p < NPOS) ? g_raw[p * 2048 + cbs + x] : 0.f;
    }
    __syncthreads();
#pragma unroll
    for (int j = y; j < 32; j += 8) {
        int p = pb + x;
        if (p < NPOS) g_cvt[(cbs + j) * NPOS + p] = tile[x][j];
    }
}

// ---------------------------------------------------------------------------
// Kernel 3: adaptive-LIF, pure flat float4 streaming. 1800 blocks x 256.
// ---------------------------------------------------------------------------
__global__ __launch_bounds__(256) void lif_kernel(
    const float* __restrict__ fb,   const float* __restrict__ soma,
    const float* __restrict__ spk,  const float* __restrict__ acur,
    const float* __restrict__ bt,   float* __restrict__ out)
{
    const int f = blockIdx.x * 256 + threadIdx.x;   // float4 index < 460800
    const int bc = f / 225;
    const int r  = f - bc * 225;
    const int cf = (bc & 63) * 225 + r;

    const float4 spkv = ((const float4*)spk)[f];
    const float4 btv  = ((const float4*)bt)[f];
    const float4 acv  = ((const float4*)acur)[f];
    const float4 fbv  = ((const float4*)fb)[f];
    const float4 somv = ((const float4*)soma)[f];
    const float4 cvtv = ((const float4*)g_cvt)[f];
    const float4 alv  = ((const float4*)g_alpha)[cf];
    const float4 rhv  = ((const float4*)g_rho)[cf];
    const float4 etv  = ((const float4*)g_eta)[cf];

    float4 o0, o1, o2, o3;
    {
        float bnew = rhv.x * btv.x + (1.f - rhv.x) * spkv.x;
        float thre = 0.1f + 1.8f * bnew;
        float anew = etv.x * acv.x + fbv.x;
        float sig  = __fdividef(1.f, 1.f + __expf(-anew)) - 0.5f;
        float sm   = alv.x * somv.x + sig + cvtv.x - thre * spkv.x;
        o0.x = sm; o1.x = (sm - thre) > 0.f ? 1.f : 0.f; o2.x = anew; o3.x = bnew;
    }
    {
        float bnew = rhv.y * btv.y + (1.f - rhv.y) * spkv.y;
        float thre = 0.1f + 1.8f * bnew;
        float anew = etv.y * acv.y + fbv.y;
        float sig  = __fdividef(1.f, 1.f + __expf(-anew)) - 0.5f;
        float sm   = alv.y * somv.y + sig + cvtv.y - thre * spkv.y;
        o0.y = sm; o1.y = (sm - thre) > 0.f ? 1.f : 0.f; o2.y = anew; o3.y = bnew;
    }
    {
        float bnew = rhv.z * btv.z + (1.f - rhv.z) * spkv.z;
        float thre = 0.1f + 1.8f * bnew;
        float anew = etv.z * acv.z + fbv.z;
        float sig  = __fdividef(1.f, 1.f + __expf(-anew)) - 0.5f;
        float sm   = alv.z * somv.z + sig + cvtv.z - thre * spkv.z;
        o0.z = sm; o1.z = (sm - thre) > 0.f ? 1.f : 0.f; o2.z = anew; o3.z = bnew;
    }
    {
        float bnew = rhv.w * btv.w + (1.f - rhv.w) * spkv.w;
        float thre = 0.1f + 1.8f * bnew;
        float anew = etv.w * acv.w + fbv.w;
        float sig  = __fdividef(1.f, 1.f + __expf(-anew)) - 0.5f;
        float sm   = alv.w * somv.w + sig + cvtv.w - thre * spkv.w;
        o0.w = sm; o1.w = (sm - thre) > 0.f ? 1.f : 0.f; o2.w = anew; o3.w = bnew;
    }

    float4* out4 = (float4*)out;
    out4[f]               = o0;
    out4[460800 + f]      = o1;
    out4[2 * 460800 + f]  = o2;
    out4[3 * 460800 + f]  = o3;
}

// ---------------------------------------------------------------------------
extern "C" void kernel_launch(void* const* d_in, const int* in_sizes, int n_in,
                              void* d_out, int out_size)
{
    const float* ff    = (const float*)d_in[0];
    const float* fb    = (const float*)d_in[1];
    const float* soma  = (const float*)d_in[2];
    const float* spk   = (const float*)d_in[3];
    const float* acur  = (const float*)d_in[4];
    const float* bt    = (const float*)d_in[5];
    const float* cw    = (const float*)d_in[6];
    const float* cbias = (const float*)d_in[7];
    const float* gamma = (const float*)d_in[8];
    const float* beta  = (const float*)d_in[9];
    const float* lrec  = (const float*)d_in[10];
    const float* tm    = (const float*)d_in[11];
    const float* tadp  = (const float*)d_in[12];
    const float* ta    = (const float*)d_in[13];
    float* out = (float*)d_out;

    cudaFuncSetAttribute(conv_kernel,
                         cudaFuncAttributeMaxDynamicSharedMemorySize, 57344);
    transpose_spk<<<dim3(29, 64), 256>>>(spk);                 // 1
    prep_kernel<<<225, 256>>>(tm, tadp, ta);                   // 2
    zero_ctr<<<1, 1>>>();                                      // 3
    conv_kernel<<<dim3(15, 30), 128, 57344>>>(ff, cw, cbias, gamma, beta); // 4
    rec_kernel<<<900, 128>>>(lrec);                            // 5
    transpose_cvt<<<dim3(29, 64), 256>>>();                    // 6
    lif_kernel<<<1800, 256>>>(fb, soma, spk, acur, bt, out);   // 7
}

// round 13
// speedup vs baseline: 1.0086x; 1.0086x over previous
#include <cuda_runtime.h>

#define BB    32
#define HO    30
#define NPOS  900
#define NELEM 1843200

// Scratch (no allocation allowed)
__device__ float g_raw[NPOS * 2048];    // conv output, then conv_total; [p][b][o]
__device__ float g_spk_t[NPOS * 2048];  // spk transposed to [p][b*64+c]
__device__ float g_cvt[2048 * NPOS];    // conv_total transposed to [bc][p]
__device__ float g_part[900 * 128];     // bn partials per conv block
__device__ float g_scale[64];
__device__ float g_shift[64];
__device__ float g_alpha[64 * NPOS];    // exp(-0.5/tm)
__device__ float g_rho[64 * NPOS];      // exp(-0.5/tadp)
__device__ float g_eta[64 * NPOS];      // exp(-0.5/ta)
__device__ unsigned g_ctr = 0;          // last-block ticket

__device__ __forceinline__ void cp4(unsigned dst, const float* src) {
    asm volatile("cp.async.ca.shared.global [%0], [%1], 4;" :: "r"(dst), "l"(src));
}

// ---------------------------------------------------------------------------
// Kernel 1: locally-connected conv + fused BN statistics.
// Grid (30,30): ONE position per block, 128 threads. 6 blocks/SM:
// smem 2 x 14336 B double buffer, thread tile 4b x 4o (acc 32 regs).
// Staging (warp-coherent):
//   W: warp wid owns c4=wid; 32 insts, lanes 0..17 = 2 o-runs of 9 floats.
//   P: 12 insts/warp, 8 runs of 3 floats (kw) per inst.
// ---------------------------------------------------------------------------
#define WROW  38
#define PBASE 2432           // 64*38 floats of W, then P 32*36
#define BUFSZ 3584           // floats per buffer (14336 B)

__global__ __launch_bounds__(128, 6) void conv_kernel(
    const float* __restrict__ ff, const float* __restrict__ cw,
    const float* __restrict__ cbias,
    const float* __restrict__ gamma, const float* __restrict__ beta)
{
    extern __shared__ float smem[];
    const unsigned sbase = (unsigned)__cvta_generic_to_shared(smem);

    const int h   = blockIdx.y;
    const int w   = blockIdx.x;
    const int tid = threadIdx.x;
    const int lane = tid & 31;
    const int wid  = tid >> 5;

    // --- staging precompute ---
    const int base9  = (h * HO + w) * 9;
    const int wl_pos = (lane >= 9) ? 1 : 0;          // which o of the pair
    const int wl_k   = lane - 9 * wl_pos;
    const unsigned wdst0 = (unsigned)(wl_pos * WROW + wid * 9 + wl_k) * 4u;
    const float* wsrc0 = cw + (wl_pos * 64 + wid) * 8100 + base9 + wl_k;

    const int pe    = lane & 3;                      // kw (active if <3)
    const int rbase = wid * 96 + (lane >> 2);        // P run base
    const int base32 = h * 32 + w;

    auto stage = [&](int cb, unsigned boff) {
        // W: 32 insts per warp, 2 runs (o=2i, 2i+1) each
        if (lane < 18) {
            const float* ws = wsrc0 + cb * (4 * 8100);
#pragma unroll
            for (int i = 0; i < 32; i++)
                cp4(sbase + boff + wdst0 + (unsigned)(i * (2 * WROW)) * 4u,
                    ws + i * (128 * 8100));
        }
        // P: 12 insts per warp, 8 runs of 3
        if (pe < 3) {
#pragma unroll
            for (int i = 0; i < 12; i++) {
                int r   = rbase + i * 8;
                int kh  = r >> 7;
                int rem = r & 127;
                int b   = rem >> 2;
                int c4  = rem & 3;
                cp4(sbase + boff +
                        (unsigned)(PBASE + b * 36 + c4 * 9 + kh * 3 + pe) * 4u,
                    ff + ((b * 64 + cb * 4 + c4) << 10) + base32 + (kh << 5) + pe);
            }
        }
    };

    // ---- GEMM roles: 4b x 4o per thread ----
    const int og = tid & 15;      // o = og + 16*jo
    const int bg = tid >> 4;      // b = bg + 8*ib  (bg 0..7)

    unsigned long long acc[4][4];
#pragma unroll
    for (int ib = 0; ib < 4; ib++)
#pragma unroll
        for (int jo = 0; jo < 4; jo++) acc[ib][jo] = 0ULL;

    stage(0, 0u);
    asm volatile("cp.async.commit_group;");

#pragma unroll 1
    for (int cb = 0; cb < 16; cb++) {
        const int buf = cb & 1;
        asm volatile("cp.async.wait_group 0;");   // chunk cb resident
        __syncthreads();                          // all warps done with buf^1
        if (cb + 1 < 16) {
            stage(cb + 1, (unsigned)((buf ^ 1) * BUFSZ) * 4u);
            asm volatile("cp.async.commit_group;");
        }

        const float* Wp = smem + buf * BUFSZ + og * WROW;
        const float* Pp = smem + buf * BUFSZ + PBASE + bg * 36;
#pragma unroll
        for (int kk = 0; kk < 18; kk++) {
            unsigned long long wv[4], pv[4];
#pragma unroll
            for (int jo = 0; jo < 4; jo++)
                wv[jo] = *(const unsigned long long*)(Wp + jo * (16 * WROW) + 2 * kk);
#pragma unroll
            for (int ib = 0; ib < 4; ib++)
                pv[ib] = *(const unsigned long long*)(Pp + ib * (8 * 36) + 2 * kk);
#pragma unroll
            for (int ib = 0; ib < 4; ib++)
#pragma unroll
                for (int jo = 0; jo < 4; jo++)
                    asm("fma.rn.f32x2 %0, %1, %2, %0;"
                        : "+l"(acc[ib][jo]) : "l"(pv[ib]), "l"(wv[jo]));
        }
    }

    // ---- epilogue: write raw conv + per-thread BN partials ----
    const int p = h * HO + w;
    float* outp = g_raw + p * 2048;
    float cb4[4];
#pragma unroll
    for (int jo = 0; jo < 4; jo++) cb4[jo] = cbias[(og + 16 * jo) * NPOS + p];
    float ps[4] = {0.f, 0.f, 0.f, 0.f}, pq[4] = {0.f, 0.f, 0.f, 0.f};
#pragma unroll
    for (int ib = 0; ib < 4; ib++) {
        const int b = bg + 8 * ib;
#pragma unroll
        for (int jo = 0; jo < 4; jo++) {
            float2 f = *reinterpret_cast<float2*>(&acc[ib][jo]);
            float v = f.x + f.y + cb4[jo];
            outp[b * 64 + og + 16 * jo] = v;
            ps[jo] += v;
            pq[jo] += v * v;
        }
    }

    // ---- block-level BN partial reduction (reuse dynamic smem) ----
    __syncthreads();
    float* red = smem;                 // [64][8] sums, [64][8] sumsq at +512
#pragma unroll
    for (int jo = 0; jo < 4; jo++) {
        red[(og + 16 * jo) * 8 + bg]       = ps[jo];
        red[512 + (og + 16 * jo) * 8 + bg] = pq[jo];
    }
    __syncthreads();
    if (tid < 64) {
        float s = 0.f, q = 0.f;
#pragma unroll
        for (int k = 0; k < 8; k++) {
            s += red[tid * 8 + k];
            q += red[512 + tid * 8 + k];
        }
        const int bid = blockIdx.y * HO + blockIdx.x;
        g_part[bid * 128 + tid]      = s;
        g_part[bid * 128 + 64 + tid] = q;
    }
    __threadfence();
    __syncthreads();
    __shared__ unsigned s_last;
    if (tid == 0) s_last = (atomicAdd(&g_ctr, 1u) == 899u) ? 1u : 0u;
    __syncthreads();
    if (s_last) {
        const int o   = tid & 63;
        const int seg = tid >> 6;      // 0..1
        float s = 0.f, q = 0.f;
#pragma unroll 15
        for (int k = seg; k < 900; k += 2) {
            s += g_part[k * 128 + o];
            q += g_part[k * 128 + 64 + o];
        }
        red[seg * 64 + o]       = s;
        red[128 + seg * 64 + o] = q;
        __syncthreads();
        if (tid < 64) {
            float S = red[tid] + red[64 + tid];
            float Q = red[128 + tid] + red[192 + tid];
            const float inv = 1.f / 28800.f;
            float m   = S * inv;
            float var = Q * inv - m * m;
            float sc  = gamma[tid] * rsqrtf(var + 1e-5f);
            g_scale[tid] = sc;
            g_shift[tid] = beta[tid] - m * sc;
        }
        if (tid == 0) g_ctr = 0;
    }
}

// ---------------------------------------------------------------------------
// Kernel T1: transpose spk [bc][p] -> [p][bc]
// ---------------------------------------------------------------------------
__global__ __launch_bounds__(256) void transpose_spk(const float* __restrict__ spk)
{
    __shared__ float tile[32][33];
    const int pb = blockIdx.x * 32;
    const int cbs = blockIdx.y * 32;
    const int x = threadIdx.x & 31;
    const int y = threadIdx.x >> 5;
#pragma unroll
    for (int j = y; j < 32; j += 8) {
        int p = pb + x;
        tile[j][x] = (p < NPOS) ? spk[(cbs + j) * NPOS + p] : 0.f;
    }
    __syncthreads();
#pragma unroll
    for (int j = y; j < 32; j += 8) {
        int p = pb + j;
        if (p < NPOS) g_spk_t[p * 2048 + cbs + x] = tile[x][j];
    }
}

// ---------------------------------------------------------------------------
// Kernel P: precompute LIF decay factors per (c,p). 225 blocks x 256.
// ---------------------------------------------------------------------------
__global__ __launch_bounds__(256) void prep_kernel(
    const float* __restrict__ tm, const float* __restrict__ tadp,
    const float* __restrict__ ta)
{
    const int i = blockIdx.x * 256 + threadIdx.x;   // < 57600
    g_alpha[i] = __expf(-__fdividef(0.5f, tm[i]));
    g_rho[i]   = __expf(-__fdividef(0.5f, tadp[i]));
    g_eta[i]   = __expf(-__fdividef(0.5f, ta[i]));
}

// ---------------------------------------------------------------------------
// Kernel Z: reset conv ticket (keeps conv as 4th launch for ncu)
// ---------------------------------------------------------------------------
__global__ void zero_ctr(void) { g_ctr = 0; }

// ---------------------------------------------------------------------------
// Kernel 2: per-position recurrence GEMM + BN apply, in-place into g_raw.
// ---------------------------------------------------------------------------
__global__ __launch_bounds__(128) void rec_kernel(const float* __restrict__ lrec)
{
    const int p = blockIdx.x;
    const int t = threadIdx.x;
    __shared__ float R[64 * 68];
    __shared__ float S[32 * 68];
    __shared__ float sc[64], sh[64];

    const float4* rp = (const float4*)(lrec + p * 4096);
#pragma unroll
    for (int i = 0; i < 8; i++) {
        int idx4 = i * 128 + t;
        int c = idx4 >> 4, d0 = (idx4 & 15) << 2;
        *(float4*)&R[c * 68 + d0] = rp[idx4];
    }
    const float4* sp = (const float4*)(g_spk_t + p * 2048);
#pragma unroll
    for (int i = 0; i < 4; i++) {
        int idx4 = i * 128 + t;
        int b = idx4 >> 4, d0 = (idx4 & 15) << 2;
        *(float4*)&S[b * 68 + d0] = sp[idx4];
    }
    if (t < 64) { sc[t] = g_scale[t]; sh[t] = g_shift[t]; }
    __syncthreads();

    const int cg = t & 15;
    const int bq = t >> 4;
    float racc[4][4];
#pragma unroll
    for (int jb = 0; jb < 4; jb++)
#pragma unroll
        for (int jc = 0; jc < 4; jc++) racc[jb][jc] = 0.f;

#pragma unroll
    for (int d = 0; d < 64; d += 4) {
        float4 rv[4], sv[4];
#pragma unroll
        for (int jc = 0; jc < 4; jc++)
            rv[jc] = *(const float4*)&R[(cg + 16 * jc) * 68 + d];
#pragma unroll
        for (int jb = 0; jb < 4; jb++)
            sv[jb] = *(const float4*)&S[(4 * bq + jb) * 68 + d];
#pragma unroll
        for (int jb = 0; jb < 4; jb++)
#pragma unroll
            for (int jc = 0; jc < 4; jc++) {
                float a = racc[jb][jc];
                a = fmaf(rv[jc].x, sv[jb].x, a);
                a = fmaf(rv[jc].y, sv[jb].y, a);
                a = fmaf(rv[jc].z, sv[jb].z, a);
                a = fmaf(rv[jc].w, sv[jb].w, a);
                racc[jb][jc] = a;
            }
    }

    float* outp = g_raw + p * 2048;
#pragma unroll
    for (int jb = 0; jb < 4; jb++) {
        const int b = 4 * bq + jb;
#pragma unroll
        for (int jc = 0; jc < 4; jc++) {
            const int c = cg + 16 * jc;
            outp[b * 64 + c] = outp[b * 64 + c] * sc[c] + sh[c] + racc[jb][jc];
        }
    }
}

// ---------------------------------------------------------------------------
// Kernel T2: transpose conv_total [p][bc] -> [bc][p]
// ---------------------------------------------------------------------------
__global__ __launch_bounds__(256) void transpose_cvt(void)
{
    __shared__ float tile[32][33];
    const int pb  = blockIdx.x * 32;
    const int cbs = blockIdx.y * 32;
    const int x = threadIdx.x & 31;
    const int y = threadIdx.x >> 5;
#pragma unroll
    for (int j = y; j < 32; j += 8) {
        int p = pb + j;
        tile[j][x] = (p < NPOS) ? g_raw[p * 2048 + cbs + x] : 0.f;
    }
    __syncthreads();
#pragma unroll
    for (int j = y; j < 32; j += 8) {
        int p = pb + x;
        if (p < NPOS) g_cvt[(cbs + j) * NPOS + p] = tile[x][j];
    }
}

// ---------------------------------------------------------------------------
// Kernel 3: adaptive-LIF, pure flat float4 streaming. 1800 blocks x 256.
// ---------------------------------------------------------------------------
__global__ __launch_bounds__(256) void lif_kernel(
    const float* __restrict__ fb,   const float* __restrict__ soma,
    const float* __restrict__ spk,  const float* __restrict__ acur,
    const float* __restrict__ bt,   float* __restrict__ out)
{
    const int f = blockIdx.x * 256 + threadIdx.x;   // float4 index < 460800
    const int bc = f / 225;
    const int r  = f - bc * 225;
    const int cf = (bc & 63) * 225 + r;

    const float4 spkv = ((const float4*)spk)[f];
    const float4 btv  = ((const float4*)bt)[f];
    const float4 acv  = ((const float4*)acur)[f];
    const float4 fbv  = ((const float4*)fb)[f];
    const float4 somv = ((const float4*)soma)[f];
    const float4 cvtv = ((const float4*)g_cvt)[f];
    const float4 alv  = ((const float4*)g_alpha)[cf];
    const float4 rhv  = ((const float4*)g_rho)[cf];
    const float4 etv  = ((const float4*)g_eta)[cf];

    float4 o0, o1, o2, o3;
    {
        float bnew = rhv.x * btv.x + (1.f - rhv.x) * spkv.x;
        float thre = 0.1f + 1.8f * bnew;
        float anew = etv.x * acv.x + fbv.x;
        float sig  = __fdividef(1.f, 1.f + __expf(-anew)) - 0.5f;
        float sm   = alv.x * somv.x + sig + cvtv.x - thre * spkv.x;
        o0.x = sm; o1.x = (sm - thre) > 0.f ? 1.f : 0.f; o2.x = anew; o3.x = bnew;
    }
    {
        float bnew = rhv.y * btv.y + (1.f - rhv.y) * spkv.y;
        float thre = 0.1f + 1.8f * bnew;
        float anew = etv.y * acv.y + fbv.y;
        float sig  = __fdividef(1.f, 1.f + __expf(-anew)) - 0.5f;
        float sm   = alv.y * somv.y + sig + cvtv.y - thre * spkv.y;
        o0.y = sm; o1.y = (sm - thre) > 0.f ? 1.f : 0.f; o2.y = anew; o3.y = bnew;
    }
    {
        float bnew = rhv.z * btv.z + (1.f - rhv.z) * spkv.z;
        float thre = 0.1f + 1.8f * bnew;
        float anew = etv.z * acv.z + fbv.z;
        float sig  = __fdividef(1.f, 1.f + __expf(-anew)) - 0.5f;
        float sm   = alv.z * somv.z + sig + cvtv.z - thre * spkv.z;
        o0.z = sm; o1.z = (sm - thre) > 0.f ? 1.f : 0.f; o2.z = anew; o3.z = bnew;
    }
    {
        float bnew = rhv.w * btv.w + (1.f - rhv.w) * spkv.w;
        float thre = 0.1f + 1.8f * bnew;
        float anew = etv.w * acv.w + fbv.w;
        float sig  = __fdividef(1.f, 1.f + __expf(-anew)) - 0.5f;
        float sm   = alv.w * somv.w + sig + cvtv.w - thre * spkv.w;
        o0.w = sm; o1.w = (sm - thre) > 0.f ? 1.f : 0.f; o2.w = anew; o3.w = bnew;
    }

    float4* out4 = (float4*)out;
    out4[f]               = o0;
    out4[460800 + f]      = o1;
    out4[2 * 460800 + f]  = o2;
    out4[3 * 460800 + f]  = o3;
}

// ---------------------------------------------------------------------------
extern "C" void kernel_launch(void* const* d_in, const int* in_sizes, int n_in,
                              void* d_out, int out_size)
{
    const float* ff    = (const float*)d_in[0];
    const float* fb    = (const float*)d_in[1];
    const float* soma  = (const float*)d_in[2];
    const float* spk   = (const float*)d_in[3];
    const float* acur  = (const float*)d_in[4];
    const float* bt    = (const float*)d_in[5];
    const float* cw    = (const float*)d_in[6];
    const float* cbias = (const float*)d_in[7];
    const float* gamma = (const float*)d_in[8];
    const float* beta  = (const float*)d_in[9];
    const float* lrec  = (const float*)d_in[10];
    const float* tm    = (const float*)d_in[11];
    const float* tadp  = (const float*)d_in[12];
    const float* ta    = (const float*)d_in[13];
    float* out = (float*)d_out;

    cudaFuncSetAttribute(conv_kernel,
                         cudaFuncAttributeMaxDynamicSharedMemorySize, 28672);
    transpose_spk<<<dim3(29, 64), 256>>>(spk);                 // 1
    prep_kernel<<<225, 256>>>(tm, tadp, ta);                   // 2
    zero_ctr<<<1, 1>>>();                                      // 3
    conv_kernel<<<dim3(30, 30), 128, 28672>>>(ff, cw, cbias, gamma, beta); // 4
    rec_kernel<<<900, 128>>>(lrec);                            // 5
    transpose_cvt<<<dim3(29, 64), 256>>>();                    // 6
    lif_kernel<<<1800, 256>>>(fb, soma, spk, acur, bt, out);   // 7
}

// round 14
// speedup vs baseline: 1.0088x; 1.0002x over previous
#include <cuda_runtime.h>

#define BB    32
#define HO    30
#define NPOS  900
#define NELEM 1843200

// Scratch (no allocation allowed)
__device__ float g_raw[NPOS * 2048];    // conv output, then conv_total; [p][b][o]
__device__ float g_spk_t[NPOS * 2048];  // spk transposed to [p][b*64+c]
__device__ float g_cvt[2048 * NPOS];    // conv_total transposed to [bc][p]
__device__ float g_part[900 * 128];     // bn partials per conv block
__device__ float g_scale[64];
__device__ float g_shift[64];
__device__ float g_alpha[64 * NPOS];    // exp(-0.5/tm)
__device__ float g_rho[64 * NPOS];      // exp(-0.5/tadp)
__device__ float g_eta[64 * NPOS];      // exp(-0.5/ta)
__device__ unsigned g_ctr = 0;          // last-block ticket

__device__ __forceinline__ void cp4(unsigned dst, const float* src) {
    asm volatile("cp.async.ca.shared.global [%0], [%1], 4;" :: "r"(dst), "l"(src));
}

// ---------------------------------------------------------------------------
// Kernel 1: locally-connected conv + fused BN statistics.
// Grid (30,30): ONE position per block, 128 threads. 6 blocks/SM:
// smem 2 x 14336 B double buffer, thread tile 4b x 4o (acc 32 regs).
// Staging (warp-coherent):
//   W: warp wid owns c4=wid; 32 insts, lanes 0..17 = 2 o-runs of 9 floats.
//   P: 12 insts/warp, 8 runs of 3 floats (kw) per inst.
// ---------------------------------------------------------------------------
#define WROW  38
#define PBASE 2432           // 64*38 floats of W, then P 32*36
#define BUFSZ 3584           // floats per buffer (14336 B)

__global__ __launch_bounds__(128, 6) void conv_kernel(
    const float* __restrict__ ff, const float* __restrict__ cw,
    const float* __restrict__ cbias,
    const float* __restrict__ gamma, const float* __restrict__ beta)
{
    extern __shared__ float smem[];
    const unsigned sbase = (unsigned)__cvta_generic_to_shared(smem);

    const int h   = blockIdx.y;
    const int w   = blockIdx.x;
    const int tid = threadIdx.x;
    const int lane = tid & 31;
    const int wid  = tid >> 5;

    // --- staging precompute ---
    const int base9  = (h * HO + w) * 9;
    const int wl_pos = (lane >= 9) ? 1 : 0;          // which o of the pair
    const int wl_k   = lane - 9 * wl_pos;
    const unsigned wdst0 = (unsigned)(wl_pos * WROW + wid * 9 + wl_k) * 4u;
    const float* wsrc0 = cw + (wl_pos * 64 + wid) * 8100 + base9 + wl_k;

    const int pe    = lane & 3;                      // kw (active if <3)
    const int rbase = wid * 96 + (lane >> 2);        // P run base
    const int base32 = h * 32 + w;

    auto stage = [&](int cb, unsigned boff) {
        // W: 32 insts per warp, 2 runs (o=2i, 2i+1) each
        if (lane < 18) {
            const float* ws = wsrc0 + cb * (4 * 8100);
#pragma unroll
            for (int i = 0; i < 32; i++)
                cp4(sbase + boff + wdst0 + (unsigned)(i * (2 * WROW)) * 4u,
                    ws + i * (128 * 8100));
        }
        // P: 12 insts per warp, 8 runs of 3
        if (pe < 3) {
#pragma unroll
            for (int i = 0; i < 12; i++) {
                int r   = rbase + i * 8;
                int kh  = r >> 7;
                int rem = r & 127;
                int b   = rem >> 2;
                int c4  = rem & 3;
                cp4(sbase + boff +
                        (unsigned)(PBASE + b * 36 + c4 * 9 + kh * 3 + pe) * 4u,
                    ff + ((b * 64 + cb * 4 + c4) << 10) + base32 + (kh << 5) + pe);
            }
        }
    };

    // ---- GEMM roles: 4b x 4o per thread ----
    const int og = tid & 15;      // o = og + 16*jo
    const int bg = tid >> 4;      // b = bg + 8*ib  (bg 0..7)

    unsigned long long acc[4][4];
#pragma unroll
    for (int ib = 0; ib < 4; ib++)
#pragma unroll
        for (int jo = 0; jo < 4; jo++) acc[ib][jo] = 0ULL;

    stage(0, 0u);
    asm volatile("cp.async.commit_group;");

#pragma unroll 1
    for (int cb = 0; cb < 16; cb++) {
        const int buf = cb & 1;
        asm volatile("cp.async.wait_group 0;");   // chunk cb resident
        __syncthreads();                          // all warps done with buf^1
        if (cb + 1 < 16) {
            stage(cb + 1, (unsigned)((buf ^ 1) * BUFSZ) * 4u);
            asm volatile("cp.async.commit_group;");
        }

        const float* Wp = smem + buf * BUFSZ + og * WROW;
        const float* Pp = smem + buf * BUFSZ + PBASE + bg * 36;
#pragma unroll
        for (int kk = 0; kk < 18; kk++) {
            unsigned long long wv[4], pv[4];
#pragma unroll
            for (int jo = 0; jo < 4; jo++)
                wv[jo] = *(const unsigned long long*)(Wp + jo * (16 * WROW) + 2 * kk);
#pragma unroll
            for (int ib = 0; ib < 4; ib++)
                pv[ib] = *(const unsigned long long*)(Pp + ib * (8 * 36) + 2 * kk);
#pragma unroll
            for (int ib = 0; ib < 4; ib++)
#pragma unroll
                for (int jo = 0; jo < 4; jo++)
                    asm("fma.rn.f32x2 %0, %1, %2, %0;"
                        : "+l"(acc[ib][jo]) : "l"(pv[ib]), "l"(wv[jo]));
        }
    }

    // ---- epilogue: write raw conv + per-thread BN partials ----
    const int p = h * HO + w;
    float* outp = g_raw + p * 2048;
    float cb4[4];
#pragma unroll
    for (int jo = 0; jo < 4; jo++) cb4[jo] = cbias[(og + 16 * jo) * NPOS + p];
    float ps[4] = {0.f, 0.f, 0.f, 0.f}, pq[4] = {0.f, 0.f, 0.f, 0.f};
#pragma unroll
    for (int ib = 0; ib < 4; ib++) {
        const int b = bg + 8 * ib;
#pragma unroll
        for (int jo = 0; jo < 4; jo++) {
            float2 f = *reinterpret_cast<float2*>(&acc[ib][jo]);
            float v = f.x + f.y + cb4[jo];
            outp[b * 64 + og + 16 * jo] = v;
            ps[jo] += v;
            pq[jo] += v * v;
        }
    }

    // ---- block-level BN partial reduction (reuse dynamic smem) ----
    __syncthreads();
    float* red = smem;                 // [64][8] sums, [64][8] sumsq at +512
#pragma unroll
    for (int jo = 0; jo < 4; jo++) {
        red[(og + 16 * jo) * 8 + bg]       = ps[jo];
        red[512 + (og + 16 * jo) * 8 + bg] = pq[jo];
    }
    __syncthreads();
    if (tid < 64) {
        float s = 0.f, q = 0.f;
#pragma unroll
        for (int k = 0; k < 8; k++) {
            s += red[tid * 8 + k];
            q += red[512 + tid * 8 + k];
        }
        const int bid = blockIdx.y * HO + blockIdx.x;
        g_part[bid * 128 + tid]      = s;
        g_part[bid * 128 + 64 + tid] = q;
    }
    __threadfence();
    __syncthreads();
    __shared__ unsigned s_last;
    if (tid == 0) s_last = (atomicAdd(&g_ctr, 1u) == 899u) ? 1u : 0u;
    __syncthreads();
    if (s_last) {
        const int o   = tid & 63;
        const int seg = tid >> 6;      // 0..1
        float s = 0.f, q = 0.f;
#pragma unroll 15
        for (int k = seg; k < 900; k += 2) {
            s += g_part[k * 128 + o];
            q += g_part[k * 128 + 64 + o];
        }
        red[seg * 64 + o]       = s;
        red[128 + seg * 64 + o] = q;
        __syncthreads();
        if (tid < 64) {
            float S = red[tid] + red[64 + tid];
            float Q = red[128 + tid] + red[192 + tid];
            const float inv = 1.f / 28800.f;
            float m   = S * inv;
            float var = Q * inv - m * m;
            float sc  = gamma[tid] * rsqrtf(var + 1e-5f);
            g_scale[tid] = sc;
            g_shift[tid] = beta[tid] - m * sc;
        }
        if (tid == 0) g_ctr = 0;
    }
}

// ---------------------------------------------------------------------------
// Kernel T1: transpose spk [bc][p] -> [p][bc]
// ---------------------------------------------------------------------------
__global__ __launch_bounds__(256) void transpose_spk(const float* __restrict__ spk)
{
    __shared__ float tile[32][33];
    const int pb = blockIdx.x * 32;
    const int cbs = blockIdx.y * 32;
    const int x = threadIdx.x & 31;
    const int y = threadIdx.x >> 5;
#pragma unroll
    for (int j = y; j < 32; j += 8) {
        int p = pb + x;
        tile[j][x] = (p < NPOS) ? spk[(cbs + j) * NPOS + p] : 0.f;
    }
    __syncthreads();
#pragma unroll
    for (int j = y; j < 32; j += 8) {
        int p = pb + j;
        if (p < NPOS) g_spk_t[p * 2048 + cbs + x] = tile[x][j];
    }
}

// ---------------------------------------------------------------------------
// Kernel P: precompute LIF decay factors per (c,p). 225 blocks x 256.
// ---------------------------------------------------------------------------
__global__ __launch_bounds__(256) void prep_kernel(
    const float* __restrict__ tm, const float* __restrict__ tadp,
    const float* __restrict__ ta)
{
    const int i = blockIdx.x * 256 + threadIdx.x;   // < 57600
    g_alpha[i] = __expf(-__fdividef(0.5f, tm[i]));
    g_rho[i]   = __expf(-__fdividef(0.5f, tadp[i]));
    g_eta[i]   = __expf(-__fdividef(0.5f, ta[i]));
}

// ---------------------------------------------------------------------------
// Kernel Z: reset conv ticket (keeps conv as 4th launch for ncu)
// ---------------------------------------------------------------------------
__global__ void zero_ctr(void) { g_ctr = 0; }

// ---------------------------------------------------------------------------
// Kernel 2: per-position recurrence GEMM + BN apply, in-place into g_raw.
// ---------------------------------------------------------------------------
__global__ __launch_bounds__(128) void rec_kernel(const float* __restrict__ lrec)
{
    const int p = blockIdx.x;
    const int t = threadIdx.x;
    __shared__ float R[64 * 68];
    __shared__ float S[32 * 68];
    __shared__ float sc[64], sh[64];

    const float4* rp = (const float4*)(lrec + p * 4096);
#pragma unroll
    for (int i = 0; i < 8; i++) {
        int idx4 = i * 128 + t;
        int c = idx4 >> 4, d0 = (idx4 & 15) << 2;
        *(float4*)&R[c * 68 + d0] = rp[idx4];
    }
    const float4* sp = (const float4*)(g_spk_t + p * 2048);
#pragma unroll
    for (int i = 0; i < 4; i++) {
        int idx4 = i * 128 + t;
        int b = idx4 >> 4, d0 = (idx4 & 15) << 2;
        *(float4*)&S[b * 68 + d0] = sp[idx4];
    }
    if (t < 64) { sc[t] = g_scale[t]; sh[t] = g_shift[t]; }
    __syncthreads();

    const int cg = t & 15;
    const int bq = t >> 4;
    float racc[4][4];
#pragma unroll
    for (int jb = 0; jb < 4; jb++)
#pragma unroll
        for (int jc = 0; jc < 4; jc++) racc[jb][jc] = 0.f;

#pragma unroll
    for (int d = 0; d < 64; d += 4) {
        float4 rv[4], sv[4];
#pragma unroll
        for (int jc = 0; jc < 4; jc++)
            rv[jc] = *(const float4*)&R[(cg + 16 * jc) * 68 + d];
#pragma unroll
        for (int jb = 0; jb < 4; jb++)
            sv[jb] = *(const float4*)&S[(4 * bq + jb) * 68 + d];
#pragma unroll
        for (int jb = 0; jb < 4; jb++)
#pragma unroll
            for (int jc = 0; jc < 4; jc++) {
                float a = racc[jb][jc];
                a = fmaf(rv[jc].x, sv[jb].x, a);
                a = fmaf(rv[jc].y, sv[jb].y, a);
                a = fmaf(rv[jc].z, sv[jb].z, a);
                a = fmaf(rv[jc].w, sv[jb].w, a);
                racc[jb][jc] = a;
            }
    }

    float* outp = g_raw + p * 2048;
#pragma unroll
    for (int jb = 0; jb < 4; jb++) {
        const int b = 4 * bq + jb;
#pragma unroll
        for (int jc = 0; jc < 4; jc++) {
            const int c = cg + 16 * jc;
            outp[b * 64 + c] = outp[b * 64 + c] * sc[c] + sh[c] + racc[jb][jc];
        }
    }
}

// ---------------------------------------------------------------------------
// Kernel T2: transpose conv_total [p][bc] -> [bc][p]
// ---------------------------------------------------------------------------
__global__ __launch_bounds__(256) void transpose_cvt(void)
{
    __shared__ float tile[32][33];
    const int pb  = blockIdx.x * 32;
    const int cbs = blockIdx.y * 32;
    const int x = threadIdx.x & 31;
    const int y = threadIdx.x >> 5;
#pragma unroll
    for (int j = y; j < 32; j += 8) {
        int p = pb + j;
        tile[j][x] = (p < NPOS) ? g_raw[p * 2048 + cbs + x] : 0.f;
    }
    __syncthreads();
#pragma unroll
    for (int j = y; j < 32; j += 8) {
        int p = pb + x;
        if (p < NPOS) g_cvt[(cbs + j) * NPOS + p] = tile[x][j];
    }
}

// ---------------------------------------------------------------------------
// Kernel 3: adaptive-LIF, pure flat float4 streaming. 1800 blocks x 256.
// ---------------------------------------------------------------------------
__global__ __launch_bounds__(256) void lif_kernel(
    const float* __restrict__ fb,   const float* __restrict__ soma,
    const float* __restrict__ spk,  const float* __restrict__ acur,
    const float* __restrict__ bt,   float* __restrict__ out)
{
    const int f = blockIdx.x * 256 + threadIdx.x;   // float4 index < 460800
    const int bc = f / 225;
    const int r  = f - bc * 225;
    const int cf = (bc & 63) * 225 + r;

    const float4 spkv = ((const float4*)spk)[f];
    const float4 btv  = ((const float4*)bt)[f];
    const float4 acv  = ((const float4*)acur)[f];
    const float4 fbv  = ((const float4*)fb)[f];
    const float4 somv = ((const float4*)soma)[f];
    const float4 cvtv = ((const float4*)g_cvt)[f];
    const float4 alv  = ((const float4*)g_alpha)[cf];
    const float4 rhv  = ((const float4*)g_rho)[cf];
    const float4 etv  = ((const float4*)g_eta)[cf];

    float4 o0, o1, o2, o3;
    {
        float bnew = rhv.x * btv.x + (1.f - rhv.x) * spkv.x;
        float thre = 0.1f + 1.8f * bnew;
        float anew = etv.x * acv.x + fbv.x;
        float sig  = __fdividef(1.f, 1.f + __expf(-anew)) - 0.5f;
        float sm   = alv.x * somv.x + sig + cvtv.x - thre * spkv.x;
        o0.x = sm; o1.x = (sm - thre) > 0.f ? 1.f : 0.f; o2.x = anew; o3.x = bnew;
    }
    {
        float bnew = rhv.y * btv.y + (1.f - rhv.y) * spkv.y;
        float thre = 0.1f + 1.8f * bnew;
        float anew = etv.y * acv.y + fbv.y;
        float sig  = __fdividef(1.f, 1.f + __expf(-anew)) - 0.5f;
        float sm   = alv.y * somv.y + sig + cvtv.y - thre * spkv.y;
        o0.y = sm; o1.y = (sm - thre) > 0.f ? 1.f : 0.f; o2.y = anew; o3.y = bnew;
    }
    {
        float bnew = rhv.z * btv.z + (1.f - rhv.z) * spkv.z;
        float thre = 0.1f + 1.8f * bnew;
        float anew = etv.z * acv.z + fbv.z;
        float sig  = __fdividef(1.f, 1.f + __expf(-anew)) - 0.5f;
        float sm   = alv.z * somv.z + sig + cvtv.z - thre * spkv.z;
        o0.z = sm; o1.z = (sm - thre) > 0.f ? 1.f : 0.f; o2.z = anew; o3.z = bnew;
    }
    {
        float bnew = rhv.w * btv.w + (1.f - rhv.w) * spkv.w;
        float thre = 0.1f + 1.8f * bnew;
        float anew = etv.w * acv.w + fbv.w;
        float sig  = __fdividef(1.f, 1.f + __expf(-anew)) - 0.5f;
        float sm   = alv.w * somv.w + sig + cvtv.w - thre * spkv.w;
        o0.w = sm; o1.w = (sm - thre) > 0.f ? 1.f : 0.f; o2.w = anew; o3.w = bnew;
    }

    float4* out4 = (float4*)out;
    out4[f]               = o0;
    out4[460800 + f]      = o1;
    out4[2 * 460800 + f]  = o2;
    out4[3 * 460800 + f]  = o3;
}

// ---------------------------------------------------------------------------
extern "C" void kernel_launch(void* const* d_in, const int* in_sizes, int n_in,
                              void* d_out, int out_size)
{
    const float* ff    = (const float*)d_in[0];
    const float* fb    = (const float*)d_in[1];
    const float* soma  = (const float*)d_in[2];
    const float* spk   = (const float*)d_in[3];
    const float* acur  = (const float*)d_in[4];
    const float* bt    = (const float*)d_in[5];
    const float* cw    = (const float*)d_in[6];
    const float* cbias = (const float*)d_in[7];
    const float* gamma = (const float*)d_in[8];
    const float* beta  = (const float*)d_in[9];
    const float* lrec  = (const float*)d_in[10];
    const float* tm    = (const float*)d_in[11];
    const float* tadp  = (const float*)d_in[12];
    const float* ta    = (const float*)d_in[13];
    float* out = (float*)d_out;

    cudaFuncSetAttribute(conv_kernel,
                         cudaFuncAttributeMaxDynamicSharedMemorySize, 28672);
    transpose_spk<<<dim3(29, 64), 256>>>(spk);                 // 1
    prep_kernel<<<225, 256>>>(tm, tadp, ta);                   // 2
    zero_ctr<<<1, 1>>>();                                      // 3
    conv_kernel<<<dim3(30, 30), 128, 28672>>>(ff, cw, cbias, gamma, beta); // 4
    rec_kernel<<<900, 128>>>(lrec);                            // 5
    transpose_cvt<<<dim3(29, 64), 256>>>();                    // 6
    lif_kernel<<<1800, 256>>>(fb, soma, spk, acur, bt, out);   // 7
}